// round 5
// baseline (speedup 1.0000x reference)
#include <cuda_runtime.h>
#include <cuda_bf16.h>
#include <math.h>
#include <stdint.h>

// Problem constants
#define B_  64
#define I_  320
#define H_  1536
#define L_  3
#define O_  256
#define H3_ 4608

#define GH_SPLIT 2
#define GI_SPLIT 8
#define I2H_SPLIT 5
#define H2O_SPLIT 24

#define KC 64           // bf16 K elements per smem stage (128B row)
#define TM 128          // weight rows per block (MMA M side)

// dynamic smem: two stages of (Whi 16K | Wlo 16K | Ahi 8K | Alo 8K)
#define SM_WHI   0
#define SM_WLO   16384
#define SM_AHI   32768
#define SM_ALO   40960
#define STAGE    49152
#define SM_TOTAL (2 * STAGE)

// Device scratch (static, no allocation)
__device__ float g_gh[GH_SPLIT * L_ * H3_ * B_];    // [l][p][j][b]
__device__ float g_gi_part[GI_SPLIT * H3_ * B_];    // [p][j][b] (also i2h scratch)
__device__ float g_inp[B_ * H_];                    // [b][h]
__device__ float g_out_part[H2O_SPLIT * O_ * B_];   // [p][o][b]

__device__ __forceinline__ uint32_t smem_u32(const void* p) {
    uint32_t a;
    asm("{ .reg .u64 t; cvta.to.shared.u64 t, %1; cvt.u32.u64 %0, t; }" : "=r"(a) : "l"(p));
    return a;
}

// split float pair into bf16-hi pair and bf16-lo (residual) pair, packed 2x16
__device__ __forceinline__ void split2(float a, float b, uint32_t& hi, uint32_t& lo) {
    __nv_bfloat16 ha = __float2bfloat16_rn(a);
    __nv_bfloat16 hb = __float2bfloat16_rn(b);
    float ra = a - __bfloat162float(ha);
    float rb = b - __bfloat162float(hb);
    hi = ((uint32_t)__bfloat16_as_ushort(hb) << 16) | (uint32_t)__bfloat16_as_ushort(ha);
    asm("cvt.rn.bf16x2.f32 %0, %1, %2;" : "=r"(lo) : "f"(rb), "f"(ra));
}

#define LDM_X4(r, addr)                                                        \
    asm volatile("ldmatrix.sync.aligned.m8n8.x4.shared.b16 {%0,%1,%2,%3}, [%4];" \
                 : "=r"((r)[0]), "=r"((r)[1]), "=r"((r)[2]), "=r"((r)[3])      \
                 : "r"(addr))

#define MMA_BF16(c, a, b0, b1)                                                 \
    asm volatile("mma.sync.aligned.m16n8k16.row.col.f32.bf16.bf16.f32 "        \
                 "{%0,%1,%2,%3}, {%4,%5,%6,%7}, {%8,%9}, {%0,%1,%2,%3};"       \
                 : "+f"((c)[0]), "+f"((c)[1]), "+f"((c)[2]), "+f"((c)[3])      \
                 : "r"((a)[0]), "r"((a)[1]), "r"((a)[2]), "r"((a)[3]),         \
                   "r"(b0), "r"(b1))

// ---------------------------------------------------------------------------
// Cpart[p][j][b] = sum_{k in chunk} W[j][k] * Act[b][k]  (3-term bf16 split)
// Double-buffered pipeline, 2 CTAs/SM.
// ---------------------------------------------------------------------------
__global__ __launch_bounds__(256, 2)
void gemm_tc_kernel(const float* __restrict__ Act,
                    const float* __restrict__ W,
                    float* __restrict__ Cpart,
                    int N, int K, int kChunk,
                    long aBatchStride, long wBatchStride, long cBatchStride)
{
    extern __shared__ __align__(128) unsigned char smem[];

    const int tid  = threadIdx.x;
    const int wid  = tid >> 5;
    const int lane = tid & 31;
    const int j0    = blockIdx.x * TM;
    const int kBase = blockIdx.y * kChunk;
    const int nChunks = kChunk / KC;

    Act += (long)blockIdx.z * aBatchStride;
    W   += (long)blockIdx.z * wBatchStride;
    Cpart += (long)blockIdx.z * cBatchStride + (long)blockIdx.y * (long)N * B_;

    // ---- loader mapping ----
    const int wr  = tid >> 1;           // W row 0..127
    const int wk0 = (tid & 1) * 32;     // fp32 k offset within chunk
    const int ar  = tid >> 2;           // Act row 0..63
    const int ak0 = (tid & 3) * 16;
    const int wChunk0 = (tid & 1) * 4;  // 16B chunk base in bf16 row
    const int aChunk0 = (tid & 3) * 2;
    const int wr7 = wr & 7, ar7 = ar & 7;

    // ---- mma mapping: 8 warps = 4(M) x 2(N); warp tile 32x32 ----
    const int wm = wid & 3;
    const int wn = wid >> 2;
    const int r7 = lane & 7;
    const int aRow = lane & 15;
    const int aKhi = lane >> 4;
    const int bNoff = (lane & 7) + ((lane >> 4) << 3);
    const int bKhi = (lane >> 3) & 1;

    const uint32_t smemB = smem_u32(smem);

    uint32_t aRowOff[2], bRowOff[2];
    aRowOff[0] = (uint32_t)(wm * 32 + aRow) * 128;
    aRowOff[1] = aRowOff[0] + 16 * 128;
    bRowOff[0] = (uint32_t)(wn * 32 + bNoff) * 128;
    bRowOff[1] = bRowOff[0] + 16 * 128;

    float acc[2][4][4];
#pragma unroll
    for (int mt = 0; mt < 2; mt++)
#pragma unroll
        for (int nt = 0; nt < 4; nt++)
#pragma unroll
            for (int q = 0; q < 4; q++) acc[mt][nt][q] = 0.0f;

    float4 wv[8], av[4];
    const float* wSrc = W + (long)(j0 + wr) * K + kBase + wk0;
    const float* aSrc = Act + (long)ar * K + kBase + ak0;

    // ---- prologue: load + convert + store chunk 0 into stage 0 ----
#pragma unroll
    for (int q = 0; q < 8; q++) wv[q] = *reinterpret_cast<const float4*>(wSrc + q * 4);
#pragma unroll
    for (int q = 0; q < 4; q++) av[q] = *reinterpret_cast<const float4*>(aSrc + q * 4);

    {
        unsigned char* st = smem;  // stage 0
        uint32_t whi[16], wlo[16], ahi[8], alo[8];
#pragma unroll
        for (int q = 0; q < 8; q++) {
            split2(wv[q].x, wv[q].y, whi[2 * q], wlo[2 * q]);
            split2(wv[q].z, wv[q].w, whi[2 * q + 1], wlo[2 * q + 1]);
        }
#pragma unroll
        for (int q = 0; q < 4; q++) {
            split2(av[q].x, av[q].y, ahi[2 * q], alo[2 * q]);
            split2(av[q].z, av[q].w, ahi[2 * q + 1], alo[2 * q + 1]);
        }
#pragma unroll
        for (int g = 0; g < 4; g++) {
            uint32_t off = (uint32_t)wr * 128 + (uint32_t)(((wChunk0 + g) ^ wr7) << 4);
            *reinterpret_cast<uint4*>(st + SM_WHI + off) =
                make_uint4(whi[4 * g], whi[4 * g + 1], whi[4 * g + 2], whi[4 * g + 3]);
            *reinterpret_cast<uint4*>(st + SM_WLO + off) =
                make_uint4(wlo[4 * g], wlo[4 * g + 1], wlo[4 * g + 2], wlo[4 * g + 3]);
        }
#pragma unroll
        for (int g = 0; g < 2; g++) {
            uint32_t off = (uint32_t)ar * 128 + (uint32_t)(((aChunk0 + g) ^ ar7) << 4);
            *reinterpret_cast<uint4*>(st + SM_AHI + off) =
                make_uint4(ahi[4 * g], ahi[4 * g + 1], ahi[4 * g + 2], ahi[4 * g + 3]);
            *reinterpret_cast<uint4*>(st + SM_ALO + off) =
                make_uint4(alo[4 * g], alo[4 * g + 1], alo[4 * g + 2], alo[4 * g + 3]);
        }
    }
    __syncthreads();

    for (int c = 0; c < nChunks; ++c) {
        // ---- issue LDGs for chunk c+1 (overlap with MMA below) ----
        const bool more = (c + 1 < nChunks);
        if (more) {
            const float* ws = wSrc + (c + 1) * KC;
            const float* as = aSrc + (c + 1) * KC;
#pragma unroll
            for (int q = 0; q < 8; q++) wv[q] = *reinterpret_cast<const float4*>(ws + q * 4);
#pragma unroll
            for (int q = 0; q < 4; q++) av[q] = *reinterpret_cast<const float4*>(as + q * 4);
        }

        // ---- MMA on stage c&1 ----
        const uint32_t sb = smemB + (uint32_t)(c & 1) * STAGE;
#pragma unroll
        for (int s = 0; s < 4; s++) {
            uint32_t aH[2][4], aL[2][4], bH[2][4], bL[2][4];
            const uint32_t ac = (uint32_t)(((2 * s + aKhi) ^ r7) << 4);
            LDM_X4(aH[0], sb + SM_WHI + aRowOff[0] + ac);
            LDM_X4(aH[1], sb + SM_WHI + aRowOff[1] + ac);
            LDM_X4(aL[0], sb + SM_WLO + aRowOff[0] + ac);
            LDM_X4(aL[1], sb + SM_WLO + aRowOff[1] + ac);
            const uint32_t bc = (uint32_t)(((2 * s + bKhi) ^ r7) << 4);
            LDM_X4(bH[0], sb + SM_AHI + bRowOff[0] + bc);
            LDM_X4(bH[1], sb + SM_AHI + bRowOff[1] + bc);
            LDM_X4(bL[0], sb + SM_ALO + bRowOff[0] + bc);
            LDM_X4(bL[1], sb + SM_ALO + bRowOff[1] + bc);
#pragma unroll
            for (int mt = 0; mt < 2; mt++)
#pragma unroll
                for (int nt = 0; nt < 4; nt++) {
                    const int pr = nt >> 1, hf = (nt & 1) * 2;
                    MMA_BF16(acc[mt][nt], aH[mt], bH[pr][hf], bH[pr][hf + 1]);
                    MMA_BF16(acc[mt][nt], aH[mt], bL[pr][hf], bL[pr][hf + 1]);
                    MMA_BF16(acc[mt][nt], aL[mt], bH[pr][hf], bH[pr][hf + 1]);
                }
        }

        // ---- convert + store chunk c+1 into the other stage ----
        if (more) {
            unsigned char* st = smem + ((c + 1) & 1) * STAGE;
            uint32_t whi[16], wlo[16], ahi[8], alo[8];
#pragma unroll
            for (int q = 0; q < 8; q++) {
                split2(wv[q].x, wv[q].y, whi[2 * q], wlo[2 * q]);
                split2(wv[q].z, wv[q].w, whi[2 * q + 1], wlo[2 * q + 1]);
            }
#pragma unroll
            for (int q = 0; q < 4; q++) {
                split2(av[q].x, av[q].y, ahi[2 * q], alo[2 * q]);
                split2(av[q].z, av[q].w, ahi[2 * q + 1], alo[2 * q + 1]);
            }
#pragma unroll
            for (int g = 0; g < 4; g++) {
                uint32_t off = (uint32_t)wr * 128 + (uint32_t)(((wChunk0 + g) ^ wr7) << 4);
                *reinterpret_cast<uint4*>(st + SM_WHI + off) =
                    make_uint4(whi[4 * g], whi[4 * g + 1], whi[4 * g + 2], whi[4 * g + 3]);
                *reinterpret_cast<uint4*>(st + SM_WLO + off) =
                    make_uint4(wlo[4 * g], wlo[4 * g + 1], wlo[4 * g + 2], wlo[4 * g + 3]);
            }
#pragma unroll
            for (int g = 0; g < 2; g++) {
                uint32_t off = (uint32_t)ar * 128 + (uint32_t)(((aChunk0 + g) ^ ar7) << 4);
                *reinterpret_cast<uint4*>(st + SM_AHI + off) =
                    make_uint4(ahi[4 * g], ahi[4 * g + 1], ahi[4 * g + 2], ahi[4 * g + 3]);
                *reinterpret_cast<uint4*>(st + SM_ALO + off) =
                    make_uint4(alo[4 * g], alo[4 * g + 1], alo[4 * g + 2], alo[4 * g + 3]);
            }
        }
        __syncthreads();
    }

    // ---- epilogue: write partial sums, layout [j][b] ----
#pragma unroll
    for (int mt = 0; mt < 2; mt++)
#pragma unroll
        for (int nt = 0; nt < 4; nt++) {
            const int j = j0 + wm * 32 + mt * 16 + (lane >> 2);
            const int b = wn * 32 + nt * 8 + (lane & 3) * 2;
            float2 v0 = make_float2(acc[mt][nt][0], acc[mt][nt][1]);
            float2 v1 = make_float2(acc[mt][nt][2], acc[mt][nt][3]);
            *reinterpret_cast<float2*>(&Cpart[(long)j * B_ + b]) = v0;
            *reinterpret_cast<float2*>(&Cpart[(long)(j + 8) * B_ + b]) = v1;
        }
}

// ---------------------------------------------------------------------------
// out[b][j] = bias[j] + sum_p parts[p][j][b]   (transposing combine)
// ---------------------------------------------------------------------------
__global__ void combine_t_kernel(const float* __restrict__ parts, int nsplit,
                                 const float* __restrict__ bias,
                                 float* __restrict__ out, int N)
{
    int idx = blockIdx.x * 256 + threadIdx.x;
    if (idx >= N * B_) return;
    int j = idx >> 6;
    int b = idx & 63;
    float s = bias[j];
    for (int p = 0; p < nsplit; p++) s += parts[(long)p * N * B_ + idx];
    out[(long)b * N + j] = s;
}

// ---------------------------------------------------------------------------
// GRU gate fusion; gi/gh partials in [p][j(4608)][b] layout.
// ---------------------------------------------------------------------------
__global__ void gru_gate_kernel(const float* __restrict__ giParts,
                                const float* __restrict__ ghParts,
                                const float* __restrict__ b_ih,
                                const float* __restrict__ b_hh,
                                const float* __restrict__ h_prev,   // [b][h]
                                float* __restrict__ h_out)          // [b][h]
{
    int idx = blockIdx.x * 256 + threadIdx.x;
    if (idx >= B_ * H_) return;
    int j = idx >> 6;
    int b = idx & 63;

    float gir = b_ih[j], giz = b_ih[H_ + j], gin = b_ih[2 * H_ + j];
#pragma unroll
    for (int p = 0; p < GI_SPLIT; p++) {
        const float* P = giParts + (long)p * H3_ * B_;
        gir += P[(long)j * B_ + b];
        giz += P[(long)(H_ + j) * B_ + b];
        gin += P[(long)(2 * H_ + j) * B_ + b];
    }
    float ghr = b_hh[j], ghz = b_hh[H_ + j], ghn = b_hh[2 * H_ + j];
#pragma unroll
    for (int p = 0; p < GH_SPLIT; p++) {
        const float* P = ghParts + (long)p * H3_ * B_;
        ghr += P[(long)j * B_ + b];
        ghz += P[(long)(H_ + j) * B_ + b];
        ghn += P[(long)(2 * H_ + j) * B_ + b];
    }

    float r = 1.0f / (1.0f + expf(-(gir + ghr)));
    float z = 1.0f / (1.0f + expf(-(giz + ghz)));
    float n = tanhf(gin + r * ghn);
    float hp = h_prev[(long)b * H_ + j];
    h_out[(long)b * H_ + j] = (1.0f - z) * n + z * hp;
}

// ---------------------------------------------------------------------------
extern "C" void kernel_launch(void* const* d_in, const int* in_sizes, int n_in,
                              void* d_out, int out_size)
{
    const float* x      = (const float*)d_in[0];   // [64,320]
    const float* hidden = (const float*)d_in[1];   // [3,64,1536]
    const float* w_i2h  = (const float*)d_in[2];   // [1536,320]
    const float* b_i2h  = (const float*)d_in[3];   // [1536]
    const float* w_ih   = (const float*)d_in[4];   // [3,4608,1536]
    const float* w_hh   = (const float*)d_in[5];   // [3,4608,1536]
    const float* b_ih   = (const float*)d_in[6];   // [3,4608]
    const float* b_hh   = (const float*)d_in[7];   // [3,4608]
    const float* w_h2o  = (const float*)d_in[8];   // [256,1536]
    const float* b_h2o  = (const float*)d_in[9];   // [256]
    (void)in_sizes; (void)n_in; (void)out_size;

    float* out     = (float*)d_out;                // [64,256]
    float* hid_out = (float*)d_out + B_ * O_;      // [3,64,1536]

    float *gh_ptr, *gi_ptr, *inp_ptr, *outp_ptr;
    cudaGetSymbolAddress((void**)&gh_ptr,   g_gh);
    cudaGetSymbolAddress((void**)&gi_ptr,   g_gi_part);
    cudaGetSymbolAddress((void**)&inp_ptr,  g_inp);
    cudaGetSymbolAddress((void**)&outp_ptr, g_out_part);

    cudaFuncSetAttribute(gemm_tc_kernel, cudaFuncAttributeMaxDynamicSharedMemorySize, SM_TOTAL);

    const long wLayerStride = (long)H3_ * H_;
    const long hLayerStride = (long)B_ * H_;
    const long ghLayerStride = (long)GH_SPLIT * H3_ * B_;

    // 1) gh for all 3 layers, batched, split-K=2: grid (36, 2, 3), 12-chunk pipeline
    gemm_tc_kernel<<<dim3(H3_ / TM, GH_SPLIT, L_), 256, SM_TOTAL>>>(
        hidden, w_hh, gh_ptr, H3_, H_, H_ / GH_SPLIT,
        hLayerStride, wLayerStride, ghLayerStride);

    // 2) i2h: split-K=5 (one 64-chunk each): grid (12, 5)
    gemm_tc_kernel<<<dim3(H_ / TM, I2H_SPLIT, 1), 256, SM_TOTAL>>>(
        x, w_i2h, gi_ptr, H_, I_, I_ / I2H_SPLIT, 0, 0, 0);
    combine_t_kernel<<<(H_ * B_ + 255) / 256, 256>>>(gi_ptr, I2H_SPLIT, b_i2h, inp_ptr, H_);

    // 3) layer chain: gi split-K=8 -> grid (36, 8) = 288 blocks (2 CTAs/SM)
    const float* inp = inp_ptr;
    for (int l = 0; l < L_; l++) {
        gemm_tc_kernel<<<dim3(H3_ / TM, GI_SPLIT, 1), 256, SM_TOTAL>>>(
            inp, w_ih + (long)l * wLayerStride, gi_ptr,
            H3_, H_, H_ / GI_SPLIT, 0, 0, 0);
        gru_gate_kernel<<<(B_ * H_ + 255) / 256, 256>>>(
            gi_ptr, gh_ptr + (long)l * ghLayerStride,
            b_ih + (long)l * H3_, b_hh + (long)l * H3_,
            hidden + (long)l * hLayerStride,
            hid_out + (long)l * hLayerStride);
        inp = hid_out + (long)l * hLayerStride;
    }

    // 4) h2o: grid (2, 24), one 64-chunk each
    gemm_tc_kernel<<<dim3(O_ / TM, H2O_SPLIT, 1), 256, SM_TOTAL>>>(
        inp, w_h2o, outp_ptr, O_, H_, H_ / H2O_SPLIT, 0, 0, 0);
    combine_t_kernel<<<(O_ * B_ + 255) / 256, 256>>>(outp_ptr, H2O_SPLIT, b_h2o, out, O_);
}

// round 6
// speedup vs baseline: 1.4917x; 1.4917x over previous
#include <cuda_runtime.h>
#include <cuda_bf16.h>
#include <math.h>
#include <stdint.h>

// Problem constants
#define B_  64
#define I_  320
#define H_  1536
#define L_  3
#define O_  256
#define H3_ 4608

#define GH_SPLIT 2
#define GI_SPLIT 8
#define I2H_SPLIT 5
#define H2O_SPLIT 24

#define KC 64           // bf16 K elements per smem stage (128B row)
#define TM 128          // weight rows per block (MMA M side)

// dynamic smem: two stages of (Whi 16K | Wlo 16K | Ahi 8K | Alo 8K)
#define SM_WHI   0
#define SM_WLO   16384
#define SM_AHI   32768
#define SM_ALO   40960
#define STAGE    49152
#define SM_TOTAL (2 * STAGE)

// Device scratch (static, no allocation)
__device__ float g_gh[GH_SPLIT * L_ * H3_ * B_];    // [l][p][j][b]
__device__ float g_gi_part[GI_SPLIT * H3_ * B_];    // [p][j][b] (also i2h scratch)
__device__ float g_inp[B_ * H_];                    // [b][h]
__device__ float g_out_part[H2O_SPLIT * O_ * B_];   // [p][o][b]

__device__ __forceinline__ uint32_t smem_u32(const void* p) {
    uint32_t a;
    asm("{ .reg .u64 t; cvta.to.shared.u64 t, %1; cvt.u32.u64 %0, t; }" : "=r"(a) : "l"(p));
    return a;
}

// split float pair into bf16-hi pair and bf16-lo (residual) pair, packed 2x16
__device__ __forceinline__ void split2(float a, float b, uint32_t& hi, uint32_t& lo) {
    __nv_bfloat16 ha = __float2bfloat16_rn(a);
    __nv_bfloat16 hb = __float2bfloat16_rn(b);
    float ra = a - __bfloat162float(ha);
    float rb = b - __bfloat162float(hb);
    hi = ((uint32_t)__bfloat16_as_ushort(hb) << 16) | (uint32_t)__bfloat16_as_ushort(ha);
    asm("cvt.rn.bf16x2.f32 %0, %1, %2;" : "=r"(lo) : "f"(rb), "f"(ra));
}

#define LDM_X4(r, addr)                                                        \
    asm volatile("ldmatrix.sync.aligned.m8n8.x4.shared.b16 {%0,%1,%2,%3}, [%4];" \
                 : "=r"((r)[0]), "=r"((r)[1]), "=r"((r)[2]), "=r"((r)[3])      \
                 : "r"(addr))

#define MMA_BF16(c, a, b0, b1)                                                 \
    asm volatile("mma.sync.aligned.m16n8k16.row.col.f32.bf16.bf16.f32 "        \
                 "{%0,%1,%2,%3}, {%4,%5,%6,%7}, {%8,%9}, {%0,%1,%2,%3};"       \
                 : "+f"((c)[0]), "+f"((c)[1]), "+f"((c)[2]), "+f"((c)[3])      \
                 : "r"((a)[0]), "r"((a)[1]), "r"((a)[2]), "r"((a)[3]),         \
                   "r"(b0), "r"(b1))

// ---------------------------------------------------------------------------
// Cpart[p][j][b] = sum_{k in chunk} W[j][k] * Act[b][k]  (3-term bf16 split)
// Double-buffered pipeline, 2 CTAs/SM.
// ---------------------------------------------------------------------------
__global__ __launch_bounds__(256, 2)
void gemm_tc_kernel(const float* __restrict__ Act,
                    const float* __restrict__ W,
                    float* __restrict__ Cpart,
                    int N, int K, int kChunk,
                    long aBatchStride, long wBatchStride, long cBatchStride)
{
    extern __shared__ __align__(128) unsigned char smem[];

    const int tid  = threadIdx.x;
    const int wid  = tid >> 5;
    const int lane = tid & 31;
    const int j0    = blockIdx.x * TM;
    const int kBase = blockIdx.y * kChunk;
    const int nChunks = kChunk / KC;

    Act += (long)blockIdx.z * aBatchStride;
    W   += (long)blockIdx.z * wBatchStride;
    Cpart += (long)blockIdx.z * cBatchStride + (long)blockIdx.y * (long)N * B_;

    // ---- loader mapping ----
    const int wr  = tid >> 1;           // W row 0..127
    const int wk0 = (tid & 1) * 32;     // fp32 k offset within chunk
    const int ar  = tid >> 2;           // Act row 0..63
    const int ak0 = (tid & 3) * 16;
    const int wChunk0 = (tid & 1) * 4;  // 16B chunk base in bf16 row
    const int aChunk0 = (tid & 3) * 2;
    const int wr7 = wr & 7, ar7 = ar & 7;

    // ---- mma mapping: 8 warps = 4(M) x 2(N); warp tile 32x32 ----
    const int wm = wid & 3;
    const int wn = wid >> 2;
    const int r7 = lane & 7;
    const int aRow = lane & 15;
    const int aKhi = lane >> 4;
    const int bNoff = (lane & 7) + ((lane >> 4) << 3);
    const int bKhi = (lane >> 3) & 1;

    const uint32_t smemB = smem_u32(smem);

    uint32_t aRowOff[2], bRowOff[2];
    aRowOff[0] = (uint32_t)(wm * 32 + aRow) * 128;
    aRowOff[1] = aRowOff[0] + 16 * 128;
    bRowOff[0] = (uint32_t)(wn * 32 + bNoff) * 128;
    bRowOff[1] = bRowOff[0] + 16 * 128;

    float acc[2][4][4];
#pragma unroll
    for (int mt = 0; mt < 2; mt++)
#pragma unroll
        for (int nt = 0; nt < 4; nt++)
#pragma unroll
            for (int q = 0; q < 4; q++) acc[mt][nt][q] = 0.0f;

    float4 wv[8], av[4];
    const float* wSrc = W + (long)(j0 + wr) * K + kBase + wk0;
    const float* aSrc = Act + (long)ar * K + kBase + ak0;

    // ---- prologue: load + convert + store chunk 0 into stage 0 ----
#pragma unroll
    for (int q = 0; q < 8; q++) wv[q] = *reinterpret_cast<const float4*>(wSrc + q * 4);
#pragma unroll
    for (int q = 0; q < 4; q++) av[q] = *reinterpret_cast<const float4*>(aSrc + q * 4);

    {
        unsigned char* st = smem;  // stage 0
        uint32_t whi[16], wlo[16], ahi[8], alo[8];
#pragma unroll
        for (int q = 0; q < 8; q++) {
            split2(wv[q].x, wv[q].y, whi[2 * q], wlo[2 * q]);
            split2(wv[q].z, wv[q].w, whi[2 * q + 1], wlo[2 * q + 1]);
        }
#pragma unroll
        for (int q = 0; q < 4; q++) {
            split2(av[q].x, av[q].y, ahi[2 * q], alo[2 * q]);
            split2(av[q].z, av[q].w, ahi[2 * q + 1], alo[2 * q + 1]);
        }
#pragma unroll
        for (int g = 0; g < 4; g++) {
            uint32_t off = (uint32_t)wr * 128 + (uint32_t)(((wChunk0 + g) ^ wr7) << 4);
            *reinterpret_cast<uint4*>(st + SM_WHI + off) =
                make_uint4(whi[4 * g], whi[4 * g + 1], whi[4 * g + 2], whi[4 * g + 3]);
            *reinterpret_cast<uint4*>(st + SM_WLO + off) =
                make_uint4(wlo[4 * g], wlo[4 * g + 1], wlo[4 * g + 2], wlo[4 * g + 3]);
        }
#pragma unroll
        for (int g = 0; g < 2; g++) {
            uint32_t off = (uint32_t)ar * 128 + (uint32_t)(((aChunk0 + g) ^ ar7) << 4);
            *reinterpret_cast<uint4*>(st + SM_AHI + off) =
                make_uint4(ahi[4 * g], ahi[4 * g + 1], ahi[4 * g + 2], ahi[4 * g + 3]);
            *reinterpret_cast<uint4*>(st + SM_ALO + off) =
                make_uint4(alo[4 * g], alo[4 * g + 1], alo[4 * g + 2], alo[4 * g + 3]);
        }
    }
    __syncthreads();

    for (int c = 0; c < nChunks; ++c) {
        // ---- issue LDGs for chunk c+1 (overlap with MMA below) ----
        const bool more = (c + 1 < nChunks);
        if (more) {
            const float* ws = wSrc + (c + 1) * KC;
            const float* as = aSrc + (c + 1) * KC;
#pragma unroll
            for (int q = 0; q < 8; q++) wv[q] = *reinterpret_cast<const float4*>(ws + q * 4);
#pragma unroll
            for (int q = 0; q < 4; q++) av[q] = *reinterpret_cast<const float4*>(as + q * 4);
        }

        // ---- MMA on stage c&1 ----
        const uint32_t sb = smemB + (uint32_t)(c & 1) * STAGE;
#pragma unroll
        for (int s = 0; s < 4; s++) {
            uint32_t aH[2][4], aL[2][4], bH[2][4], bL[2][4];
            const uint32_t ac = (uint32_t)(((2 * s + aKhi) ^ r7) << 4);
            LDM_X4(aH[0], sb + SM_WHI + aRowOff[0] + ac);
            LDM_X4(aH[1], sb + SM_WHI + aRowOff[1] + ac);
            LDM_X4(aL[0], sb + SM_WLO + aRowOff[0] + ac);
            LDM_X4(aL[1], sb + SM_WLO + aRowOff[1] + ac);
            const uint32_t bc = (uint32_t)(((2 * s + bKhi) ^ r7) << 4);
            LDM_X4(bH[0], sb + SM_AHI + bRowOff[0] + bc);
            LDM_X4(bH[1], sb + SM_AHI + bRowOff[1] + bc);
            LDM_X4(bL[0], sb + SM_ALO + bRowOff[0] + bc);
            LDM_X4(bL[1], sb + SM_ALO + bRowOff[1] + bc);
#pragma unroll
            for (int mt = 0; mt < 2; mt++)
#pragma unroll
                for (int nt = 0; nt < 4; nt++) {
                    const int pr = nt >> 1, hf = (nt & 1) * 2;
                    MMA_BF16(acc[mt][nt], aH[mt], bH[pr][hf], bH[pr][hf + 1]);
                    MMA_BF16(acc[mt][nt], aH[mt], bL[pr][hf], bL[pr][hf + 1]);
                    MMA_BF16(acc[mt][nt], aL[mt], bH[pr][hf], bH[pr][hf + 1]);
                }
        }

        // ---- convert + store chunk c+1 into the other stage ----
        if (more) {
            unsigned char* st = smem + ((c + 1) & 1) * STAGE;
            uint32_t whi[16], wlo[16], ahi[8], alo[8];
#pragma unroll
            for (int q = 0; q < 8; q++) {
                split2(wv[q].x, wv[q].y, whi[2 * q], wlo[2 * q]);
                split2(wv[q].z, wv[q].w, whi[2 * q + 1], wlo[2 * q + 1]);
            }
#pragma unroll
            for (int q = 0; q < 4; q++) {
                split2(av[q].x, av[q].y, ahi[2 * q], alo[2 * q]);
                split2(av[q].z, av[q].w, ahi[2 * q + 1], alo[2 * q + 1]);
            }
#pragma unroll
            for (int g = 0; g < 4; g++) {
                uint32_t off = (uint32_t)wr * 128 + (uint32_t)(((wChunk0 + g) ^ wr7) << 4);
                *reinterpret_cast<uint4*>(st + SM_WHI + off) =
                    make_uint4(whi[4 * g], whi[4 * g + 1], whi[4 * g + 2], whi[4 * g + 3]);
                *reinterpret_cast<uint4*>(st + SM_WLO + off) =
                    make_uint4(wlo[4 * g], wlo[4 * g + 1], wlo[4 * g + 2], wlo[4 * g + 3]);
            }
#pragma unroll
            for (int g = 0; g < 2; g++) {
                uint32_t off = (uint32_t)ar * 128 + (uint32_t)(((aChunk0 + g) ^ ar7) << 4);
                *reinterpret_cast<uint4*>(st + SM_AHI + off) =
                    make_uint4(ahi[4 * g], ahi[4 * g + 1], ahi[4 * g + 2], ahi[4 * g + 3]);
                *reinterpret_cast<uint4*>(st + SM_ALO + off) =
                    make_uint4(alo[4 * g], alo[4 * g + 1], alo[4 * g + 2], alo[4 * g + 3]);
            }
        }
        __syncthreads();
    }

    // ---- epilogue: write partial sums, layout [j][b] ----
#pragma unroll
    for (int mt = 0; mt < 2; mt++)
#pragma unroll
        for (int nt = 0; nt < 4; nt++) {
            const int j = j0 + wm * 32 + mt * 16 + (lane >> 2);
            const int b = wn * 32 + nt * 8 + (lane & 3) * 2;
            float2 v0 = make_float2(acc[mt][nt][0], acc[mt][nt][1]);
            float2 v1 = make_float2(acc[mt][nt][2], acc[mt][nt][3]);
            *reinterpret_cast<float2*>(&Cpart[(long)j * B_ + b]) = v0;
            *reinterpret_cast<float2*>(&Cpart[(long)(j + 8) * B_ + b]) = v1;
        }
}

// ---------------------------------------------------------------------------
// out[b][j] = bias[j] + sum_p parts[p][j][b]   (transposing combine)
// ---------------------------------------------------------------------------
__global__ void combine_t_kernel(const float* __restrict__ parts, int nsplit,
                                 const float* __restrict__ bias,
                                 float* __restrict__ out, int N)
{
    int idx = blockIdx.x * 256 + threadIdx.x;
    if (idx >= N * B_) return;
    int j = idx >> 6;
    int b = idx & 63;
    float s = bias[j];
    for (int p = 0; p < nsplit; p++) s += parts[(long)p * N * B_ + idx];
    out[(long)b * N + j] = s;
}

// ---------------------------------------------------------------------------
// GRU gate fusion; gi/gh partials in [p][j(4608)][b] layout.
// ---------------------------------------------------------------------------
__global__ void gru_gate_kernel(const float* __restrict__ giParts,
                                const float* __restrict__ ghParts,
                                const float* __restrict__ b_ih,
                                const float* __restrict__ b_hh,
                                const float* __restrict__ h_prev,   // [b][h]
                                float* __restrict__ h_out)          // [b][h]
{
    int idx = blockIdx.x * 256 + threadIdx.x;
    if (idx >= B_ * H_) return;
    int j = idx >> 6;
    int b = idx & 63;

    float gir = b_ih[j], giz = b_ih[H_ + j], gin = b_ih[2 * H_ + j];
#pragma unroll
    for (int p = 0; p < GI_SPLIT; p++) {
        const float* P = giParts + (long)p * H3_ * B_;
        gir += P[(long)j * B_ + b];
        giz += P[(long)(H_ + j) * B_ + b];
        gin += P[(long)(2 * H_ + j) * B_ + b];
    }
    float ghr = b_hh[j], ghz = b_hh[H_ + j], ghn = b_hh[2 * H_ + j];
#pragma unroll
    for (int p = 0; p < GH_SPLIT; p++) {
        const float* P = ghParts + (long)p * H3_ * B_;
        ghr += P[(long)j * B_ + b];
        ghz += P[(long)(H_ + j) * B_ + b];
        ghn += P[(long)(2 * H_ + j) * B_ + b];
    }

    float r = 1.0f / (1.0f + expf(-(gir + ghr)));
    float z = 1.0f / (1.0f + expf(-(giz + ghz)));
    float n = tanhf(gin + r * ghn);
    float hp = h_prev[(long)b * H_ + j];
    h_out[(long)b * H_ + j] = (1.0f - z) * n + z * hp;
}

// ---------------------------------------------------------------------------
extern "C" void kernel_launch(void* const* d_in, const int* in_sizes, int n_in,
                              void* d_out, int out_size)
{
    const float* x      = (const float*)d_in[0];   // [64,320]
    const float* hidden = (const float*)d_in[1];   // [3,64,1536]
    const float* w_i2h  = (const float*)d_in[2];   // [1536,320]
    const float* b_i2h  = (const float*)d_in[3];   // [1536]
    const float* w_ih   = (const float*)d_in[4];   // [3,4608,1536]
    const float* w_hh   = (const float*)d_in[5];   // [3,4608,1536]
    const float* b_ih   = (const float*)d_in[6];   // [3,4608]
    const float* b_hh   = (const float*)d_in[7];   // [3,4608]
    const float* w_h2o  = (const float*)d_in[8];   // [256,1536]
    const float* b_h2o  = (const float*)d_in[9];   // [256]
    (void)in_sizes; (void)n_in; (void)out_size;

    float* out     = (float*)d_out;                // [64,256]
    float* hid_out = (float*)d_out + B_ * O_;      // [3,64,1536]

    float *gh_ptr, *gi_ptr, *inp_ptr, *outp_ptr;
    cudaGetSymbolAddress((void**)&gh_ptr,   g_gh);
    cudaGetSymbolAddress((void**)&gi_ptr,   g_gi_part);
    cudaGetSymbolAddress((void**)&inp_ptr,  g_inp);
    cudaGetSymbolAddress((void**)&outp_ptr, g_out_part);

    cudaFuncSetAttribute(gemm_tc_kernel, cudaFuncAttributeMaxDynamicSharedMemorySize, SM_TOTAL);

    const long wLayerStride = (long)H3_ * H_;
    const long hLayerStride = (long)B_ * H_;
    const long ghLayerStride = (long)GH_SPLIT * H3_ * B_;

    // 1) gh for all 3 layers, batched, split-K=2: grid (36, 2, 3), 12-chunk pipeline
    gemm_tc_kernel<<<dim3(H3_ / TM, GH_SPLIT, L_), 256, SM_TOTAL>>>(
        hidden, w_hh, gh_ptr, H3_, H_, H_ / GH_SPLIT,
        hLayerStride, wLayerStride, ghLayerStride);

    // 2) i2h: split-K=5 (one 64-chunk each): grid (12, 5)
    gemm_tc_kernel<<<dim3(H_ / TM, I2H_SPLIT, 1), 256, SM_TOTAL>>>(
        x, w_i2h, gi_ptr, H_, I_, I_ / I2H_SPLIT, 0, 0, 0);
    combine_t_kernel<<<(H_ * B_ + 255) / 256, 256>>>(gi_ptr, I2H_SPLIT, b_i2h, inp_ptr, H_);

    // 3) layer chain: gi split-K=8 -> grid (36, 8) = 288 blocks (2 CTAs/SM)
    const float* inp = inp_ptr;
    for (int l = 0; l < L_; l++) {
        gemm_tc_kernel<<<dim3(H3_ / TM, GI_SPLIT, 1), 256, SM_TOTAL>>>(
            inp, w_ih + (long)l * wLayerStride, gi_ptr,
            H3_, H_, H_ / GI_SPLIT, 0, 0, 0);
        gru_gate_kernel<<<(B_ * H_ + 255) / 256, 256>>>(
            gi_ptr, gh_ptr + (long)l * ghLayerStride,
            b_ih + (long)l * H3_, b_hh + (long)l * H3_,
            hidden + (long)l * hLayerStride,
            hid_out + (long)l * hLayerStride);
        inp = hid_out + (long)l * hLayerStride;
    }

    // 4) h2o: grid (2, 24), one 64-chunk each
    gemm_tc_kernel<<<dim3(O_ / TM, H2O_SPLIT, 1), 256, SM_TOTAL>>>(
        inp, w_h2o, outp_ptr, O_, H_, H_ / H2O_SPLIT, 0, 0, 0);
    combine_t_kernel<<<(O_ * B_ + 255) / 256, 256>>>(outp_ptr, H2O_SPLIT, b_h2o, out, O_);
}

// round 7
// speedup vs baseline: 2.0267x; 1.3587x over previous
#include <cuda_runtime.h>
#include <cuda_bf16.h>
#include <math.h>
#include <stdint.h>

// Problem constants
#define B_  64
#define I_  320
#define H_  1536
#define L_  3
#define O_  256
#define H3_ 4608

#define GH_SPLIT 2
#define GI_SPLIT 8
#define I2H_SPLIT 5
#define H2O_SPLIT 24

#define KC 32            // fp32 k elements per chunk (128B row)
#define TM 128           // weight rows per block (MMA M side)
#define STAGES 4
#define STAGE_SZ 24576   // W 128x128B (16KB) + Act 64x128B (8KB)
#define SM_TOTAL (STAGES * STAGE_SZ)

// Device scratch (static, no allocation)
__device__ __align__(16) float g_gh[GH_SPLIT * L_ * H3_ * B_];   // [l][p][j][b]
__device__ __align__(16) float g_gi_part[GI_SPLIT * H3_ * B_];   // [p][j][b]
__device__ __align__(16) float g_inp[B_ * H_];                   // [b][h]
__device__ __align__(16) float g_out_part[H2O_SPLIT * O_ * B_];  // [p][o][b]

__device__ __forceinline__ uint32_t smem_u32(const void* p) {
    uint32_t a;
    asm("{ .reg .u64 t; cvta.to.shared.u64 t, %1; cvt.u32.u64 %0, t; }" : "=r"(a) : "l"(p));
    return a;
}

#define CP_ASYNC16(dst, src) \
    asm volatile("cp.async.cg.shared.global [%0], [%1], 16;" :: "r"(dst), "l"(src) : "memory")
#define CP_COMMIT() asm volatile("cp.async.commit_group;" ::: "memory")
#define CP_WAIT2()  asm volatile("cp.async.wait_group 2;" ::: "memory")

#define LDM_X4(r, addr)                                                          \
    asm volatile("ldmatrix.sync.aligned.m8n8.x4.shared.b16 {%0,%1,%2,%3}, [%4];" \
                 : "=r"((r)[0]), "=r"((r)[1]), "=r"((r)[2]), "=r"((r)[3])        \
                 : "r"(addr))

#define MMA_TF32(c, a, b0, b1)                                                   \
    asm volatile("mma.sync.aligned.m16n8k8.row.col.f32.tf32.tf32.f32 "           \
                 "{%0,%1,%2,%3}, {%4,%5,%6,%7}, {%8,%9}, {%0,%1,%2,%3};"         \
                 : "+f"((c)[0]), "+f"((c)[1]), "+f"((c)[2]), "+f"((c)[3])        \
                 : "r"((a)[0]), "r"((a)[1]), "r"((a)[2]), "r"((a)[3]),           \
                   "r"(b0), "r"(b1))

__device__ __forceinline__ uint32_t to_tf32(uint32_t x) {
    uint32_t y;
    asm("cvt.rna.tf32.f32 %0, %1;" : "=r"(y) : "f"(__uint_as_float(x)));
    return y;
}

// ---------------------------------------------------------------------------
// Cpart[z][y][j][b] = sum_{k in chunk} W[j][k] * Act[b][k]  (single-pass tf32)
// cp.async 4-stage pipeline; block tile 128(j) x 64(b); 8 warps of 32x32.
// ---------------------------------------------------------------------------
__global__ __launch_bounds__(256, 2)
void gemm_tc_kernel(const float* __restrict__ Act,
                    const float* __restrict__ W,
                    float* __restrict__ Cpart,
                    int N, int K, int kChunk,
                    long aBatchStride, long wBatchStride, long cBatchStride)
{
    extern __shared__ __align__(16) unsigned char smem[];
    const uint32_t smemB = smem_u32(smem);

    const int tid  = threadIdx.x;
    const int wid  = tid >> 5;
    const int lane = tid & 31;
    const int j0    = blockIdx.x * TM;
    const int kBase = blockIdx.y * kChunk;
    const int nChunks = kChunk >> 5;

    Act += (long)blockIdx.z * aBatchStride;
    W   += (long)blockIdx.z * wBatchStride;
    Cpart += (long)blockIdx.z * cBatchStride + (long)blockIdx.y * (long)N * B_;

    // ---- cp.async loader mapping ----
    const int wRow = tid >> 1;           // W row 0..127
    const int wG0  = (tid & 1) * 4;      // 16B-group base (4 of 8)
    const int aRow = tid >> 2;           // Act row 0..63
    const int aG0  = (tid & 3) * 2;      // 16B-group base (2 of 8)
    const float* wSrc = W + (long)(j0 + wRow) * K + kBase;
    const float* aSrc = Act + (long)aRow * K + kBase;
    const uint32_t wDstRow = wRow * 128;
    const uint32_t aDstRow = 16384 + aRow * 128;
    const int wSw = wRow & 7, aSw = aRow & 7;

    // ---- mma mapping: 8 warps = 4(M) x 2(N); warp tile 32x32 ----
    const int wm = wid & 3, wn = wid >> 2;
    const int r7 = lane & 7;
    const int aKhi = lane >> 4;                       // A: k-group parity
    const int bKhi = (lane >> 3) & 1;                 // B: k-group parity
    const int bNoff = (lane & 7) + ((lane >> 4) << 3);
    const uint32_t aOff0 = (uint32_t)(wm * 32 + (lane & 15)) * 128;
    const uint32_t aOff1 = aOff0 + 2048;              // +16 rows
    const uint32_t bOff0 = 16384 + (uint32_t)(wn * 32 + bNoff) * 128;
    const uint32_t bOff1 = bOff0 + 2048;              // +16 rows

    float acc[2][4][4];
#pragma unroll
    for (int mt = 0; mt < 2; mt++)
#pragma unroll
        for (int nt = 0; nt < 4; nt++)
#pragma unroll
            for (int q = 0; q < 4; q++) acc[mt][nt][q] = 0.0f;

    // ---- prologue: stages 0..2 ----
#pragma unroll
    for (int p = 0; p < 3; p++) {
        if (p < nChunks) {
            const uint32_t sb = smemB + (uint32_t)p * STAGE_SZ;
#pragma unroll
            for (int g = 0; g < 4; g++) {
                const int kg = wG0 + g;
                CP_ASYNC16(sb + wDstRow + ((kg ^ wSw) << 4), wSrc + p * KC + kg * 4);
            }
#pragma unroll
            for (int g = 0; g < 2; g++) {
                const int kg = aG0 + g;
                CP_ASYNC16(sb + aDstRow + ((kg ^ aSw) << 4), aSrc + p * KC + kg * 4);
            }
        }
        CP_COMMIT();
    }

    for (int c = 0; c < nChunks; ++c) {
        CP_WAIT2();
        __syncthreads();   // stage c visible to all; all warps done with stage c-1

        // issue stage c+3 (overlaps with MMA below)
        if (c + 3 < nChunks) {
            const uint32_t sb = smemB + (uint32_t)((c + 3) & 3) * STAGE_SZ;
#pragma unroll
            for (int g = 0; g < 4; g++) {
                const int kg = wG0 + g;
                CP_ASYNC16(sb + wDstRow + ((kg ^ wSw) << 4), wSrc + (c + 3) * KC + kg * 4);
            }
#pragma unroll
            for (int g = 0; g < 2; g++) {
                const int kg = aG0 + g;
                CP_ASYNC16(sb + aDstRow + ((kg ^ aSw) << 4), aSrc + (c + 3) * KC + kg * 4);
            }
        }
        CP_COMMIT();

        // ---- MMA on stage c&3: 4 k8 steps ----
        const uint32_t sb = smemB + (uint32_t)(c & 3) * STAGE_SZ;
#pragma unroll
        for (int s = 0; s < 4; s++) {
            uint32_t aF[2][4], bF[2][4];
            const uint32_t ga = (uint32_t)(((2 * s + aKhi) ^ r7) << 4);
            LDM_X4(aF[0], sb + aOff0 + ga);
            LDM_X4(aF[1], sb + aOff1 + ga);
            const uint32_t gb = (uint32_t)(((2 * s + bKhi) ^ r7) << 4);
            LDM_X4(bF[0], sb + bOff0 + gb);
            LDM_X4(bF[1], sb + bOff1 + gb);
#pragma unroll
            for (int mt = 0; mt < 2; mt++)
#pragma unroll
                for (int q = 0; q < 4; q++) aF[mt][q] = to_tf32(aF[mt][q]);
#pragma unroll
            for (int pr = 0; pr < 2; pr++)
#pragma unroll
                for (int q = 0; q < 4; q++) bF[pr][q] = to_tf32(bF[pr][q]);
#pragma unroll
            for (int mt = 0; mt < 2; mt++)
#pragma unroll
                for (int nt = 0; nt < 4; nt++) {
                    const int pr = nt >> 1, hf = (nt & 1) * 2;
                    MMA_TF32(acc[mt][nt], aF[mt], bF[pr][hf], bF[pr][hf + 1]);
                }
        }
    }

    // ---- epilogue: write partial sums, layout [j][b] ----
#pragma unroll
    for (int mt = 0; mt < 2; mt++)
#pragma unroll
        for (int nt = 0; nt < 4; nt++) {
            const int j = j0 + wm * 32 + mt * 16 + (lane >> 2);
            const int b = wn * 32 + nt * 8 + (lane & 3) * 2;
            *reinterpret_cast<float2*>(&Cpart[(long)j * B_ + b]) =
                make_float2(acc[mt][nt][0], acc[mt][nt][1]);
            *reinterpret_cast<float2*>(&Cpart[(long)(j + 8) * B_ + b]) =
                make_float2(acc[mt][nt][2], acc[mt][nt][3]);
        }
}

// ---------------------------------------------------------------------------
// out[b][j] = bias[j] + sum_p parts[p][j][b]   (transposing combine)
// ---------------------------------------------------------------------------
__global__ void combine_t_kernel(const float* __restrict__ parts, int nsplit,
                                 const float* __restrict__ bias,
                                 float* __restrict__ out, int N)
{
    int idx = blockIdx.x * 256 + threadIdx.x;
    if (idx >= N * B_) return;
    int j = idx >> 6;
    int b = idx & 63;
    float s = bias[j];
    for (int p = 0; p < nsplit; p++) s += parts[(long)p * N * B_ + idx];
    out[(long)b * N + j] = s;
}

// ---------------------------------------------------------------------------
// GRU gate fusion; gi/gh partials in [p][j(4608)][b] layout.
// ---------------------------------------------------------------------------
__global__ void gru_gate_kernel(const float* __restrict__ giParts,
                                const float* __restrict__ ghParts,
                                const float* __restrict__ b_ih,
                                const float* __restrict__ b_hh,
                                const float* __restrict__ h_prev,   // [b][h]
                                float* __restrict__ h_out)          // [b][h]
{
    int idx = blockIdx.x * 256 + threadIdx.x;
    if (idx >= B_ * H_) return;
    int j = idx >> 6;
    int b = idx & 63;

    float gir = b_ih[j], giz = b_ih[H_ + j], gin = b_ih[2 * H_ + j];
#pragma unroll
    for (int p = 0; p < GI_SPLIT; p++) {
        const float* P = giParts + (long)p * H3_ * B_;
        gir += P[(long)j * B_ + b];
        giz += P[(long)(H_ + j) * B_ + b];
        gin += P[(long)(2 * H_ + j) * B_ + b];
    }
    float ghr = b_hh[j], ghz = b_hh[H_ + j], ghn = b_hh[2 * H_ + j];
#pragma unroll
    for (int p = 0; p < GH_SPLIT; p++) {
        const float* P = ghParts + (long)p * H3_ * B_;
        ghr += P[(long)j * B_ + b];
        ghz += P[(long)(H_ + j) * B_ + b];
        ghn += P[(long)(2 * H_ + j) * B_ + b];
    }

    float r = 1.0f / (1.0f + expf(-(gir + ghr)));
    float z = 1.0f / (1.0f + expf(-(giz + ghz)));
    float n = tanhf(gin + r * ghn);
    float hp = h_prev[(long)b * H_ + j];
    h_out[(long)b * H_ + j] = (1.0f - z) * n + z * hp;
}

// ---------------------------------------------------------------------------
extern "C" void kernel_launch(void* const* d_in, const int* in_sizes, int n_in,
                              void* d_out, int out_size)
{
    const float* x      = (const float*)d_in[0];   // [64,320]
    const float* hidden = (const float*)d_in[1];   // [3,64,1536]
    const float* w_i2h  = (const float*)d_in[2];   // [1536,320]
    const float* b_i2h  = (const float*)d_in[3];   // [1536]
    const float* w_ih   = (const float*)d_in[4];   // [3,4608,1536]
    const float* w_hh   = (const float*)d_in[5];   // [3,4608,1536]
    const float* b_ih   = (const float*)d_in[6];   // [3,4608]
    const float* b_hh   = (const float*)d_in[7];   // [3,4608]
    const float* w_h2o  = (const float*)d_in[8];   // [256,1536]
    const float* b_h2o  = (const float*)d_in[9];   // [256]
    (void)in_sizes; (void)n_in; (void)out_size;

    float* out     = (float*)d_out;                // [64,256]
    float* hid_out = (float*)d_out + B_ * O_;      // [3,64,1536]

    float *gh_ptr, *gi_ptr, *inp_ptr, *outp_ptr;
    cudaGetSymbolAddress((void**)&gh_ptr,   g_gh);
    cudaGetSymbolAddress((void**)&gi_ptr,   g_gi_part);
    cudaGetSymbolAddress((void**)&inp_ptr,  g_inp);
    cudaGetSymbolAddress((void**)&outp_ptr, g_out_part);

    cudaFuncSetAttribute(gemm_tc_kernel, cudaFuncAttributeMaxDynamicSharedMemorySize, SM_TOTAL);

    const long wLayerStride = (long)H3_ * H_;
    const long hLayerStride = (long)B_ * H_;
    const long ghLayerStride = (long)GH_SPLIT * H3_ * B_;

    // 1) gh, all 3 layers, split-K=2: grid (36, 2, 3), 24-chunk pipeline
    gemm_tc_kernel<<<dim3(H3_ / TM, GH_SPLIT, L_), 256, SM_TOTAL>>>(
        hidden, w_hh, gh_ptr, H3_, H_, H_ / GH_SPLIT,
        hLayerStride, wLayerStride, ghLayerStride);

    // 2) i2h: split-K=5: grid (12, 5), 2 chunks each
    gemm_tc_kernel<<<dim3(H_ / TM, I2H_SPLIT, 1), 256, SM_TOTAL>>>(
        x, w_i2h, gi_ptr, H_, I_, I_ / I2H_SPLIT, 0, 0, 0);
    combine_t_kernel<<<(H_ * B_ + 255) / 256, 256>>>(gi_ptr, I2H_SPLIT, b_i2h, inp_ptr, H_);

    // 3) layer chain: gi split-K=8 -> grid (36, 8) = 288 blocks, 6 chunks each
    const float* inp = inp_ptr;
    for (int l = 0; l < L_; l++) {
        gemm_tc_kernel<<<dim3(H3_ / TM, GI_SPLIT, 1), 256, SM_TOTAL>>>(
            inp, w_ih + (long)l * wLayerStride, gi_ptr,
            H3_, H_, H_ / GI_SPLIT, 0, 0, 0);
        gru_gate_kernel<<<(B_ * H_ + 255) / 256, 256>>>(
            gi_ptr, gh_ptr + (long)l * ghLayerStride,
            b_ih + (long)l * H3_, b_hh + (long)l * H3_,
            hidden + (long)l * hLayerStride,
            hid_out + (long)l * hLayerStride);
        inp = hid_out + (long)l * hLayerStride;
    }

    // 4) h2o: grid (2, 24), 2 chunks each
    gemm_tc_kernel<<<dim3(O_ / TM, H2O_SPLIT, 1), 256, SM_TOTAL>>>(
        inp, w_h2o, outp_ptr, O_, H_, H_ / H2O_SPLIT, 0, 0, 0);
    combine_t_kernel<<<(O_ * B_ + 255) / 256, 256>>>(outp_ptr, H2O_SPLIT, b_h2o, out, O_);
}